// round 15
// baseline (speedup 1.0000x reference)
#include <cuda_runtime.h>
#include <cuda_fp16.h>
#include <cstdint>

#define BATCH      16
#define TSEQ       8192
#define MDIM       256
#define ROWS_TOTAL (BATCH * TSEQ)          // 131072
#define TILE_M     64
#define N_TILES    (ROWS_TOTAL / TILE_M)   // 2048
#define TILES_PER_B (TSEQ / TILE_M)        // 128
#define A_ROW_BYTES 528                    // 264 halves (256 + 8 pad)
#define A_BYTES    (TILE_M * A_ROW_BYTES)  // 33792
#define B_ROW_BYTES 144                    // 72 halves (64 + 8 pad)
#define B_BYTES    (MDIM * B_ROW_BYTES)    // 36864
#define DYN_SMEM   (1024 + A_BYTES + 2 * B_BYTES)   // 108544 (x2 CTA = 217KB/SM)

// ---------------- helpers ----------------
__device__ __forceinline__ uint32_t smem_u32(const void* p) {
    uint32_t a;
    asm("{ .reg .u64 t; cvta.to.shared.u64 t, %1; cvt.u32.u64 %0, t; }" : "=r"(a) : "l"(p));
    return a;
}
#define CP_ASYNC16(dst, src) \
    asm volatile("cp.async.cg.shared.global [%0], [%1], 16;" :: "r"(dst), "l"(src) : "memory")
#define CP_COMMIT() asm volatile("cp.async.commit_group;" ::: "memory")
#define CP_WAIT1()  asm volatile("cp.async.wait_group 1;" ::: "memory")
#define CP_WAIT0()  asm volatile("cp.async.wait_group 0;" ::: "memory")

__device__ __forceinline__ uint32_t lds_u32(uint32_t a) {
    uint32_t v;
    asm volatile("ld.shared.u32 %0, [%1];" : "=r"(v) : "r"(a));
    return v;
}
__device__ __forceinline__ void sts_u128(uint32_t a, uint32_t v0, uint32_t v1, uint32_t v2, uint32_t v3) {
    asm volatile("st.shared.v4.u32 [%0], {%1, %2, %3, %4};"
                 :: "r"(a), "r"(v0), "r"(v1), "r"(v2), "r"(v3) : "memory");
}
__device__ __forceinline__ void mma16816(float* c, const uint32_t* a, uint32_t b0, uint32_t b1) {
    asm volatile(
        "mma.sync.aligned.m16n8k16.row.col.f32.f16.f16.f32 "
        "{%0,%1,%2,%3}, {%4,%5,%6,%7}, {%8,%9}, {%0,%1,%2,%3};"
        : "+f"(c[0]), "+f"(c[1]), "+f"(c[2]), "+f"(c[3])
        : "r"(a[0]), "r"(a[1]), "r"(a[2]), "r"(a[3]), "r"(b0), "r"(b1));
}
__device__ __forceinline__ float tanh_fast(float x) {
    float y;
    asm("tanh.approx.f32 %0, %1;" : "=f"(y) : "f"(x));
    return y;
}

// ---------------- global scratch ----------------
__device__ float  ap_cb16[16][MDIM];              // cbias partials (16-way k split)
__device__ __half ap_Wt16[MDIM * MDIM];           // [n][k] = fp16(W1^T)
__device__ float  ap_partials[N_TILES * MDIM];    // per-CTA  sum_t e_t * x[t][col]
__device__ float  ap_sume[N_TILES];               // per-CTA  sum_t e_t
__device__ int    ap_cnt[BATCH];                  // per-batch completion counters

// ---------------- kernel 1: prep ----------------
// blocks 0-31: W1^T -> fp16.  blocks 32-47: cbias partials (16 k's each) + counter reset.
__global__ void __launch_bounds__(1024) ap_prep_kernel(const float* __restrict__ W1,
                                                       const float* __restrict__ W2,
                                                       const float* __restrict__ vm) {
    const int tid = threadIdx.x;
    if (blockIdx.x < 32) {
        const int n  = tid & 255;
        const int k0 = blockIdx.x * 8 + (tid >> 8) * 2;
        __half h0 = __float2half_rn(W1[k0 * MDIM + n]);         // coalesced in n
        __half h1 = __float2half_rn(W1[(k0 + 1) * MDIM + n]);
        __half2 hh = __halves2half2(h0, h1);
        *reinterpret_cast<__half2*>(ap_Wt16 + n * MDIM + k0) = hh;
    } else {
        __shared__ float part[4][MDIM];
        const int j  = blockIdx.x - 32;
        if (j == 0 && tid < BATCH) ap_cnt[tid] = 0;    // reset completion counters
        const int kq = tid >> 8;           // 0..3
        const int n  = tid & 255;
        float acc = 0.f;
        #pragma unroll
        for (int k0 = 0; k0 < 4; k0++) {
            int k = j * 16 + kq * 4 + k0;
            acc += vm[k] * W2[k * MDIM + n];
        }
        part[kq][n] = acc;
        __syncthreads();
        if (tid < MDIM)
            ap_cb16[j][tid] = part[0][tid] + part[1][tid] + part[2][tid] + part[3][tid];
    }
}

// ---------------- kernel 2: fused scores + exp + weighted sum + last-arriver reduce ----------------
__global__ void __launch_bounds__(256, 2)
ap_scores_kernel(const float* __restrict__ x, const float* __restrict__ vm,
                 float* __restrict__ out) {
    extern __shared__ char dsm[];
    __shared__ float2 cbvm[MDIM];            // 2 KB
    __shared__ float  sred[4][TILE_M];       // 1 KB
    __shared__ int    s_last;
    __shared__ float  swsum[8];

    const int tid   = threadIdx.x;
    const int wid   = tid >> 5;
    const int lane  = tid & 31;
    const int g     = lane >> 2;        // groupID
    const int tig   = lane & 3;         // thread-in-group
    const int mhalf = wid >> 2;         // rows 0-31 / 32-63
    const int nquad = wid & 3;          // cols q*64..
    const int m0    = mhalf * 32;
    const int n0    = nquad * 64;

    uint32_t raw  = smem_u32(dsm);
    uint32_t base = (raw + 1023u) & ~1023u;
    const uint32_t aA = base;                   // 64 x 264 halves
    const uint32_t aB = base + A_BYTES;         // 2 x (256 x 72 halves)
    // epilogue scratch aliased into the (then-dead) B region:
    char* dsm_base = dsm + (base - raw);
    float*  se  = reinterpret_cast<float*>(dsm_base + A_BYTES);          // 64 floats
    float2* spw = reinterpret_cast<float2*>(dsm_base + A_BYTES + 512);   // [2][128]

    const __half* wt = ap_Wt16;
    auto prefetchB = [&](int c) {
        uint32_t dstb = aB + (c & 1) * B_BYTES;
        #pragma unroll
        for (int it = 0; it < 8; it++) {
            int idx = it * 256 + tid;              // 0..2047
            int n = idx >> 3, jj = idx & 7;
            CP_ASYNC16(dstb + n * B_ROW_BYTES + jj * 16,
                       (const void*)(wt + n * MDIM + c * 64 + jj * 8));
        }
    };
    prefetchB(0);
    CP_COMMIT();

    // cbias reduction (16 L2-hot loads, overlapped with cp.async + x LDGs below)
    {
        float cb = 0.f;
        #pragma unroll
        for (int j = 0; j < 16; j++) cb += ap_cb16[j][tid];
        cbvm[tid] = make_float2(cb, vm[tid]);
    }

    // ---- load x tile (64 x 256 fp32) -> fp16 in smem ----
    const float* xt = x + (size_t)blockIdx.x * TILE_M * MDIM;
    #pragma unroll
    for (int it = 0; it < 8; it++) {
        int id   = it * 256 + tid;      // 0..2047 groups of 8 floats
        int row  = id >> 5;
        int col0 = (id & 31) * 8;
        float4 v0 = *(const float4*)(xt + row * MDIM + col0);
        float4 v1 = *(const float4*)(xt + row * MDIM + col0 + 4);
        __half2 h0 = __floats2half2_rn(v0.x, v0.y);
        __half2 h1 = __floats2half2_rn(v0.z, v0.w);
        __half2 h2 = __floats2half2_rn(v1.x, v1.y);
        __half2 h3 = __floats2half2_rn(v1.z, v1.w);
        sts_u128(aA + row * A_ROW_BYTES + col0 * 2,
                 *(uint32_t*)&h0, *(uint32_t*)&h1, *(uint32_t*)&h2, *(uint32_t*)&h3);
    }

    // fragment row offsets
    uint32_t arow[2], brow[8];
    #pragma unroll
    for (int mi = 0; mi < 2; mi++) arow[mi] = (m0 + mi * 16 + g) * A_ROW_BYTES + tig * 4;
    #pragma unroll
    for (int ni = 0; ni < 8; ni++) brow[ni] = (n0 + ni * 8 + g) * B_ROW_BYTES + tig * 4;

    float acc[2][8][4];
    #pragma unroll
    for (int mi = 0; mi < 2; mi++)
        #pragma unroll
        for (int ni = 0; ni < 8; ni++)
            #pragma unroll
            for (int j = 0; j < 4; j++) acc[mi][ni][j] = 0.f;

    // ---- main loop: 4 K=64 chunks, double-buffered B ----
    #pragma unroll
    for (int c = 0; c < 4; c++) {
        if (c < 3) { prefetchB(c + 1); CP_COMMIT(); CP_WAIT1(); }
        else       { CP_WAIT0(); }
        __syncthreads();
        uint32_t abase = aA + c * 128;
        uint32_t bbase = aB + (c & 1) * B_BYTES;
        #pragma unroll
        for (int kk = 0; kk < 4; kk++) {
            uint32_t a[2][4];
            #pragma unroll
            for (int mi = 0; mi < 2; mi++) {
                uint32_t ad = abase + arow[mi] + kk * 32;
                a[mi][0] = lds_u32(ad);
                a[mi][1] = lds_u32(ad + 8 * A_ROW_BYTES);
                a[mi][2] = lds_u32(ad + 16);
                a[mi][3] = lds_u32(ad + 8 * A_ROW_BYTES + 16);
            }
            #pragma unroll
            for (int ni = 0; ni < 8; ni++) {
                uint32_t bd = bbase + brow[ni] + kk * 32;
                uint32_t b0 = lds_u32(bd);
                uint32_t b1 = lds_u32(bd + 16);
                #pragma unroll
                for (int mi = 0; mi < 2; mi++) mma16816(acc[mi][ni], a[mi], b0, b1);
            }
        }
        __syncthreads();
    }

    // ---- epilogue A: score[r] = sum_col tanh(D + cb[col]) * vm[col] ----
    float rs[2][2];
    #pragma unroll
    for (int mi = 0; mi < 2; mi++) { rs[mi][0] = 0.f; rs[mi][1] = 0.f; }
    #pragma unroll
    for (int mi = 0; mi < 2; mi++)
        #pragma unroll
        for (int ni = 0; ni < 8; ni++)
            #pragma unroll
            for (int j = 0; j < 4; j++) {
                int col = n0 + ni * 8 + tig * 2 + (j & 1);
                float2 cv = cbvm[col];
                rs[mi][j >> 1] += tanh_fast(acc[mi][ni][j] + cv.x) * cv.y;
            }
    #pragma unroll
    for (int mi = 0; mi < 2; mi++)
        #pragma unroll
        for (int h = 0; h < 2; h++) {
            float v = rs[mi][h];
            v += __shfl_xor_sync(0xFFFFFFFFu, v, 1);
            v += __shfl_xor_sync(0xFFFFFFFFu, v, 2);
            if (tig == 0) sred[nquad][m0 + mi * 16 + h * 8 + g] = v;
        }
    __syncthreads();

    // ---- epilogue B: e = exp(score) (scores bounded; no max needed) ----
    if (tid < TILE_M) {
        float s = sred[0][tid] + sred[1][tid] + sred[2][tid] + sred[3][tid];
        se[tid] = __expf(s);
    }
    __syncthreads();

    // ---- epilogue C: partial[col] = sum_r e[r] * x_fp16[r][col] ----
    {
        const int c2 = tid & 127;       // half2 column pair
        const int rg = tid >> 7;        // row group 0/1
        float2 a2 = make_float2(0.f, 0.f);
        uint32_t ab = aA + rg * 32 * A_ROW_BYTES + c2 * 4;
        #pragma unroll 8
        for (int r = 0; r < 32; r++) {
            float e = se[rg * 32 + r];
            uint32_t p = lds_u32(ab + r * A_ROW_BYTES);
            float2 xv = __half22float2(*reinterpret_cast<__half2*>(&p));
            a2.x += e * xv.x;
            a2.y += e * xv.y;
        }
        spw[rg * 128 + c2] = a2;
    }
    // warp 4 computes sumE in parallel with the spw writes above
    if (wid == 4) {
        float s = se[lane] + se[lane + 32];
        #pragma unroll
        for (int o = 16; o > 0; o >>= 1) s += __shfl_xor_sync(0xFFFFFFFFu, s, o);
        if (lane == 0) ap_sume[blockIdx.x] = s;
    }
    __syncthreads();
    if (tid < 128) {
        float2 p0 = spw[tid], p1 = spw[128 + tid];
        float2 r = make_float2(p0.x + p1.x, p0.y + p1.y);
        *(float2*)(ap_partials + (size_t)blockIdx.x * MDIM + tid * 2) = r;
    }

    // ---- last-arriver per batch: deterministic final reduce -> out ----
    const int b = blockIdx.x / TILES_PER_B;
    __threadfence();                       // release partials + sume (all threads)
    __syncthreads();                       // order tid0's atomic after all fences
    if (tid == 0) {
        int old = atomicAdd(&ap_cnt[b], 1);
        s_last = (old == TILES_PER_B - 1);
    }
    __syncthreads();
    if (s_last) {
        __threadfence();                   // acquire: see all tiles' writes
        // fixed-order column reduce (identical arithmetic to prior ap_final2)
        float accf = 0.f;
        const float* pp = ap_partials + (size_t)b * TILES_PER_B * MDIM + tid;
        #pragma unroll 8
        for (int i = 0; i < TILES_PER_B; i++) accf += pp[(size_t)i * MDIM];
        // sumE over 128 tiles: 8 warps x 16 values each, fixed order
        {
            float s = (lane < 16) ? ap_sume[b * TILES_PER_B + wid * 16 + lane] : 0.f;
            #pragma unroll
            for (int o = 8; o > 0; o >>= 1) s += __shfl_xor_sync(0xFFFFFFFFu, s, o);
            if (lane == 0) swsum[wid] = s;
        }
        __syncthreads();
        float ssum = 0.f;
        #pragma unroll
        for (int q = 0; q < 8; q++) ssum += swsum[q];
        out[b * MDIM + tid] = accf / ssum;
    }
}

// ---------------- launch ----------------
extern "C" void kernel_launch(void* const* d_in, const int* in_sizes, int n_in,
                              void* d_out, int out_size) {
    const float* x  = (const float*)d_in[0];
    const float* W1 = (const float*)d_in[1];
    const float* W2 = (const float*)d_in[2];
    const float* vm = (const float*)d_in[3];
    float* out = (float*)d_out;

    cudaFuncSetAttribute(ap_scores_kernel, cudaFuncAttributeMaxDynamicSharedMemorySize, DYN_SMEM);

    ap_prep_kernel<<<48, 1024>>>(W1, W2, vm);
    ap_scores_kernel<<<N_TILES, 256, DYN_SMEM>>>(x, vm, out);
}

// round 16
// speedup vs baseline: 1.1702x; 1.1702x over previous
#include <cuda_runtime.h>
#include <cuda_fp16.h>
#include <cstdint>

#define BATCH      16
#define TSEQ       8192
#define MDIM       256
#define ROWS_TOTAL (BATCH * TSEQ)          // 131072
#define TILE_M     64
#define N_TILES    (ROWS_TOTAL / TILE_M)   // 2048
#define TILES_PER_B (TSEQ / TILE_M)        // 128
#define A_ROW_BYTES 528                    // 264 halves (256 + 8 pad)
#define A_BYTES    (TILE_M * A_ROW_BYTES)  // 33792
#define B_ROW_BYTES 144                    // 72 halves (64 + 8 pad)
#define B_BYTES    (MDIM * B_ROW_BYTES)    // 36864
#define DYN_SMEM   (1024 + A_BYTES + 2 * B_BYTES)   // 108544 (x2 CTA = 217KB/SM)

// ---------------- helpers ----------------
__device__ __forceinline__ uint32_t smem_u32(const void* p) {
    uint32_t a;
    asm("{ .reg .u64 t; cvta.to.shared.u64 t, %1; cvt.u32.u64 %0, t; }" : "=r"(a) : "l"(p));
    return a;
}
#define CP_ASYNC16(dst, src) \
    asm volatile("cp.async.cg.shared.global [%0], [%1], 16;" :: "r"(dst), "l"(src) : "memory")
#define CP_COMMIT() asm volatile("cp.async.commit_group;" ::: "memory")
#define CP_WAIT1()  asm volatile("cp.async.wait_group 1;" ::: "memory")
#define CP_WAIT0()  asm volatile("cp.async.wait_group 0;" ::: "memory")

__device__ __forceinline__ uint32_t lds_u32(uint32_t a) {
    uint32_t v;
    asm volatile("ld.shared.u32 %0, [%1];" : "=r"(v) : "r"(a));
    return v;
}
__device__ __forceinline__ void sts_u128(uint32_t a, uint32_t v0, uint32_t v1, uint32_t v2, uint32_t v3) {
    asm volatile("st.shared.v4.u32 [%0], {%1, %2, %3, %4};"
                 :: "r"(a), "r"(v0), "r"(v1), "r"(v2), "r"(v3) : "memory");
}
__device__ __forceinline__ void ldmatrix_x4(uint32_t& r0, uint32_t& r1, uint32_t& r2, uint32_t& r3,
                                            uint32_t addr) {
    asm volatile("ldmatrix.sync.aligned.m8n8.x4.shared.b16 {%0,%1,%2,%3}, [%4];"
                 : "=r"(r0), "=r"(r1), "=r"(r2), "=r"(r3) : "r"(addr));
}
__device__ __forceinline__ void mma16816(float* c, const uint32_t* a, uint32_t b0, uint32_t b1) {
    asm volatile(
        "mma.sync.aligned.m16n8k16.row.col.f32.f16.f16.f32 "
        "{%0,%1,%2,%3}, {%4,%5,%6,%7}, {%8,%9}, {%0,%1,%2,%3};"
        : "+f"(c[0]), "+f"(c[1]), "+f"(c[2]), "+f"(c[3])
        : "r"(a[0]), "r"(a[1]), "r"(a[2]), "r"(a[3]), "r"(b0), "r"(b1));
}
__device__ __forceinline__ float tanh_fast(float x) {
    float y;
    asm("tanh.approx.f32 %0, %1;" : "=f"(y) : "f"(x));
    return y;
}

// ---------------- global scratch ----------------
__device__ float  ap_cb16[16][MDIM];              // cbias partials (16-way k split)
__device__ __half ap_Wt16[MDIM * MDIM];           // [n][k] = fp16(W1^T)
__device__ float  ap_partials[N_TILES * MDIM];    // per-CTA  sum_t e_t * x[t][col]
__device__ float  ap_sume[N_TILES];               // per-CTA  sum_t e_t

// ---------------- kernel 1: prep ----------------
// blocks 0-31: W1^T -> fp16.  blocks 32-47: cbias partials (16 k's each).
__global__ void __launch_bounds__(1024) ap_prep_kernel(const float* __restrict__ W1,
                                                       const float* __restrict__ W2,
                                                       const float* __restrict__ vm) {
    const int tid = threadIdx.x;
    if (blockIdx.x < 32) {
        const int n  = tid & 255;
        const int k0 = blockIdx.x * 8 + (tid >> 8) * 2;
        __half h0 = __float2half_rn(W1[k0 * MDIM + n]);         // coalesced in n
        __half h1 = __float2half_rn(W1[(k0 + 1) * MDIM + n]);
        __half2 hh = __halves2half2(h0, h1);
        *reinterpret_cast<__half2*>(ap_Wt16 + n * MDIM + k0) = hh;
    } else {
        __shared__ float part[4][MDIM];
        const int j  = blockIdx.x - 32;
        const int kq = tid >> 8;           // 0..3
        const int n  = tid & 255;
        float acc = 0.f;
        #pragma unroll
        for (int k0 = 0; k0 < 4; k0++) {
            int k = j * 16 + kq * 4 + k0;
            acc += vm[k] * W2[k * MDIM + n];
        }
        part[kq][n] = acc;
        __syncthreads();
        if (tid < MDIM)
            ap_cb16[j][tid] = part[0][tid] + part[1][tid] + part[2][tid] + part[3][tid];
    }
}

// ---------------- kernel 2: fused scores + exp + weighted partial sum ----------------
__global__ void __launch_bounds__(256, 2)
ap_scores_kernel(const float* __restrict__ x, const float* __restrict__ vm) {
    extern __shared__ char dsm[];
    __shared__ float2 cbvm[MDIM];            // 2 KB
    __shared__ float  sred[4][TILE_M];       // 1 KB

    const int tid   = threadIdx.x;
    const int wid   = tid >> 5;
    const int lane  = tid & 31;
    const int g     = lane >> 2;        // groupID
    const int tig   = lane & 3;         // thread-in-group
    const int mhalf = wid >> 2;         // rows 0-31 / 32-63
    const int nquad = wid & 3;          // cols q*64..
    const int m0    = mhalf * 32;
    const int n0    = nquad * 64;

    uint32_t raw  = smem_u32(dsm);
    uint32_t base = (raw + 1023u) & ~1023u;
    const uint32_t aA = base;                   // 64 x 264 halves
    const uint32_t aB = base + A_BYTES;         // 2 x (256 x 72 halves)
    // epilogue scratch aliased into the (then-dead) B region:
    char* dsm_base = dsm + (base - raw);
    float*  se  = reinterpret_cast<float*>(dsm_base + A_BYTES);          // 64 floats
    float2* spw = reinterpret_cast<float2*>(dsm_base + A_BYTES + 512);   // [2][128]

    const __half* wt = ap_Wt16;
    auto prefetchB = [&](int c) {
        uint32_t dstb = aB + (c & 1) * B_BYTES;
        #pragma unroll
        for (int it = 0; it < 8; it++) {
            int idx = it * 256 + tid;              // 0..2047
            int n = idx >> 3, jj = idx & 7;
            CP_ASYNC16(dstb + n * B_ROW_BYTES + jj * 16,
                       (const void*)(wt + n * MDIM + c * 64 + jj * 8));
        }
    };
    prefetchB(0);
    CP_COMMIT();

    // cbias reduction (16 L2-hot loads, overlapped with cp.async + x LDGs below)
    {
        float cb = 0.f;
        #pragma unroll
        for (int j = 0; j < 16; j++) cb += ap_cb16[j][tid];
        cbvm[tid] = make_float2(cb, vm[tid]);
    }

    // ---- load x tile (64 x 256 fp32) -> fp16 in smem ----
    const float* xt = x + (size_t)blockIdx.x * TILE_M * MDIM;
    #pragma unroll
    for (int it = 0; it < 8; it++) {
        int id   = it * 256 + tid;      // 0..2047 groups of 8 floats
        int row  = id >> 5;
        int col0 = (id & 31) * 8;
        float4 v0 = *(const float4*)(xt + row * MDIM + col0);
        float4 v1 = *(const float4*)(xt + row * MDIM + col0 + 4);
        __half2 h0 = __floats2half2_rn(v0.x, v0.y);
        __half2 h1 = __floats2half2_rn(v0.z, v0.w);
        __half2 h2 = __floats2half2_rn(v1.x, v1.y);
        __half2 h3 = __floats2half2_rn(v1.z, v1.w);
        sts_u128(aA + row * A_ROW_BYTES + col0 * 2,
                 *(uint32_t*)&h0, *(uint32_t*)&h1, *(uint32_t*)&h2, *(uint32_t*)&h3);
    }

    // ldmatrix address precompute.
    // A x4 matrix order: [rows 0-7 @k+0, rows 8-15 @k+0, rows 0-7 @k+8, rows 8-15 @k+8]
    //   -> regs (a0,a1,a2,a3) of the m16k16 fragment.
    // B x4 matrix order: [ni rows @k+0, ni rows @k+8, ni+1 rows @k+0, ni+1 rows @k+8]
    //   -> (b0,b1) for ni, (b0,b1) for ni+1.
    const int l8 = lane & 7;
    const int lg = lane >> 3;           // 0..3
    uint32_t amat[2], bmat[4];
    #pragma unroll
    for (int mi = 0; mi < 2; mi++)
        amat[mi] = (uint32_t)(m0 + mi * 16 + (lg & 1) * 8 + l8) * A_ROW_BYTES
                 + (uint32_t)((lg >> 1) * 16);
    #pragma unroll
    for (int p = 0; p < 4; p++)
        bmat[p] = (uint32_t)(n0 + p * 16 + (lg >> 1) * 8 + l8) * B_ROW_BYTES
                + (uint32_t)((lg & 1) * 16);

    float acc[2][8][4];
    #pragma unroll
    for (int mi = 0; mi < 2; mi++)
        #pragma unroll
        for (int ni = 0; ni < 8; ni++)
            #pragma unroll
            for (int j = 0; j < 4; j++) acc[mi][ni][j] = 0.f;

    // ---- main loop: 4 K=64 chunks, double-buffered B, ldmatrix fragment loads ----
    #pragma unroll
    for (int c = 0; c < 4; c++) {
        if (c < 3) { prefetchB(c + 1); CP_COMMIT(); CP_WAIT1(); }
        else       { CP_WAIT0(); }
        __syncthreads();
        uint32_t abase = aA + c * 128;
        uint32_t bbase = aB + (c & 1) * B_BYTES;
        #pragma unroll
        for (int kk = 0; kk < 4; kk++) {
            uint32_t a[2][4];
            #pragma unroll
            for (int mi = 0; mi < 2; mi++)
                ldmatrix_x4(a[mi][0], a[mi][1], a[mi][2], a[mi][3],
                            abase + amat[mi] + kk * 32);
            #pragma unroll
            for (int p = 0; p < 4; p++) {
                uint32_t b0a, b1a, b0b, b1b;
                ldmatrix_x4(b0a, b1a, b0b, b1b, bbase + bmat[p] + kk * 32);
                #pragma unroll
                for (int mi = 0; mi < 2; mi++) {
                    mma16816(acc[mi][2 * p],     a[mi], b0a, b1a);
                    mma16816(acc[mi][2 * p + 1], a[mi], b0b, b1b);
                }
            }
        }
        __syncthreads();
    }

    // ---- epilogue A: score[r] = sum_col tanh(D + cb[col]) * vm[col] ----
    float rs[2][2];
    #pragma unroll
    for (int mi = 0; mi < 2; mi++) { rs[mi][0] = 0.f; rs[mi][1] = 0.f; }
    #pragma unroll
    for (int mi = 0; mi < 2; mi++)
        #pragma unroll
        for (int ni = 0; ni < 8; ni++)
            #pragma unroll
            for (int j = 0; j < 4; j++) {
                int col = n0 + ni * 8 + tig * 2 + (j & 1);
                float2 cv = cbvm[col];
                rs[mi][j >> 1] += tanh_fast(acc[mi][ni][j] + cv.x) * cv.y;
            }
    #pragma unroll
    for (int mi = 0; mi < 2; mi++)
        #pragma unroll
        for (int h = 0; h < 2; h++) {
            float v = rs[mi][h];
            v += __shfl_xor_sync(0xFFFFFFFFu, v, 1);
            v += __shfl_xor_sync(0xFFFFFFFFu, v, 2);
            if (tig == 0) sred[nquad][m0 + mi * 16 + h * 8 + g] = v;
        }
    __syncthreads();

    // ---- epilogue B: e = exp(score) (scores bounded; no max needed) ----
    if (tid < TILE_M) {
        float s = sred[0][tid] + sred[1][tid] + sred[2][tid] + sred[3][tid];
        se[tid] = __expf(s);
    }
    __syncthreads();

    // ---- epilogue C: partial[col] = sum_r e[r] * x_fp16[r][col] ----
    {
        const int c2 = tid & 127;       // half2 column pair
        const int rg = tid >> 7;        // row group 0/1
        float2 a2 = make_float2(0.f, 0.f);
        uint32_t ab = aA + rg * 32 * A_ROW_BYTES + c2 * 4;
        #pragma unroll 8
        for (int r = 0; r < 32; r++) {
            float e = se[rg * 32 + r];
            uint32_t p = lds_u32(ab + r * A_ROW_BYTES);
            float2 xv = __half22float2(*reinterpret_cast<__half2*>(&p));
            a2.x += e * xv.x;
            a2.y += e * xv.y;
        }
        spw[rg * 128 + c2] = a2;
    }
    // warp 4 computes sumE in parallel with the spw writes above
    if (wid == 4) {
        float s = se[lane] + se[lane + 32];
        #pragma unroll
        for (int o = 16; o > 0; o >>= 1) s += __shfl_xor_sync(0xFFFFFFFFu, s, o);
        if (lane == 0) ap_sume[blockIdx.x] = s;
    }
    __syncthreads();
    if (tid < 128) {
        float2 p0 = spw[tid], p1 = spw[128 + tid];
        float2 r = make_float2(p0.x + p1.x, p0.y + p1.y);
        *(float2*)(ap_partials + (size_t)blockIdx.x * MDIM + tid * 2) = r;
    }
}

// ---------------- kernel 3: final reduce -> out (16,1,256) ----------------
__global__ void __launch_bounds__(256) ap_final2_kernel(float* __restrict__ out) {
    __shared__ float sp[8][32];
    __shared__ float swsum[8];
    const int b   = blockIdx.x;
    const int cg  = blockIdx.y;
    const int tid = threadIdx.x;
    const int col = cg * 32 + (tid & 31);
    const int rg  = tid >> 5;            // 0..7

    const float* pp = ap_partials + (size_t)b * TILES_PER_B * MDIM + col;
    float acc = 0.f;
    #pragma unroll
    for (int i = 0; i < 16; i++)
        acc += pp[(size_t)(rg * 16 + i) * MDIM];
    sp[rg][tid & 31] = acc;

    // sumE over 128 tiles: 8 warps x 16 values each
    {
        const int w = tid >> 5, l = tid & 31;
        float s = (l < 16) ? ap_sume[b * TILES_PER_B + w * 16 + l] : 0.f;
        #pragma unroll
        for (int o = 8; o > 0; o >>= 1) s += __shfl_xor_sync(0xFFFFFFFFu, s, o);
        if (l == 0) swsum[w] = s;
    }
    __syncthreads();
    if (tid < 32) {
        float r = 0.f, ssum = 0.f;
        #pragma unroll
        for (int q = 0; q < 8; q++) { r += sp[q][tid]; ssum += swsum[q]; }
        out[b * MDIM + col] = r / ssum;
    }
}

// ---------------- launch ----------------
extern "C" void kernel_launch(void* const* d_in, const int* in_sizes, int n_in,
                              void* d_out, int out_size) {
    const float* x  = (const float*)d_in[0];
    const float* W1 = (const float*)d_in[1];
    const float* W2 = (const float*)d_in[2];
    const float* vm = (const float*)d_in[3];
    float* out = (float*)d_out;

    cudaFuncSetAttribute(ap_scores_kernel, cudaFuncAttributeMaxDynamicSharedMemorySize, DYN_SMEM);

    ap_prep_kernel<<<48, 1024>>>(W1, W2, vm);
    ap_scores_kernel<<<N_TILES, 256, DYN_SMEM>>>(x, vm);
    ap_final2_kernel<<<dim3(BATCH, 8), 256>>>(out);
}

// round 17
// speedup vs baseline: 1.1977x; 1.0234x over previous
#include <cuda_runtime.h>
#include <cuda_fp16.h>
#include <cstdint>

#define BATCH      16
#define TSEQ       8192
#define MDIM       256
#define ROWS_TOTAL (BATCH * TSEQ)          // 131072
#define TILE_M     64
#define N_TILES    (ROWS_TOTAL / TILE_M)   // 2048
#define TILES_PER_B (TSEQ / TILE_M)        // 128
#define A_ROW_BYTES 528                    // 264 halves (256 + 8 pad)
#define A_BYTES    (TILE_M * A_ROW_BYTES)  // 33792
#define B_ROW_BYTES 144                    // 72 halves (64 + 8 pad)
#define B_BYTES    (MDIM * B_ROW_BYTES)    // 36864
#define DYN_SMEM   (1024 + A_BYTES + 2 * B_BYTES)   // 108544 (x2 CTA = 217KB/SM)

// ---------------- helpers ----------------
__device__ __forceinline__ uint32_t smem_u32(const void* p) {
    uint32_t a;
    asm("{ .reg .u64 t; cvta.to.shared.u64 t, %1; cvt.u32.u64 %0, t; }" : "=r"(a) : "l"(p));
    return a;
}
#define CP_ASYNC16(dst, src) \
    asm volatile("cp.async.cg.shared.global [%0], [%1], 16;" :: "r"(dst), "l"(src) : "memory")
#define CP_COMMIT() asm volatile("cp.async.commit_group;" ::: "memory")
#define CP_WAIT1()  asm volatile("cp.async.wait_group 1;" ::: "memory")
#define CP_WAIT0()  asm volatile("cp.async.wait_group 0;" ::: "memory")

__device__ __forceinline__ uint32_t lds_u32(uint32_t a) {
    uint32_t v;
    asm volatile("ld.shared.u32 %0, [%1];" : "=r"(v) : "r"(a));
    return v;
}
__device__ __forceinline__ void lds_u64(uint32_t& v0, uint32_t& v1, uint32_t a) {
    asm volatile("ld.shared.v2.u32 {%0, %1}, [%2];" : "=r"(v0), "=r"(v1) : "r"(a));
}
__device__ __forceinline__ void sts_u128(uint32_t a, uint32_t v0, uint32_t v1, uint32_t v2, uint32_t v3) {
    asm volatile("st.shared.v4.u32 [%0], {%1, %2, %3, %4};"
                 :: "r"(a), "r"(v0), "r"(v1), "r"(v2), "r"(v3) : "memory");
}
__device__ __forceinline__ void ldmatrix_x4(uint32_t& r0, uint32_t& r1, uint32_t& r2, uint32_t& r3,
                                            uint32_t addr) {
    asm volatile("ldmatrix.sync.aligned.m8n8.x4.shared.b16 {%0,%1,%2,%3}, [%4];"
                 : "=r"(r0), "=r"(r1), "=r"(r2), "=r"(r3) : "r"(addr));
}
__device__ __forceinline__ void mma16816(float* c, const uint32_t* a, uint32_t b0, uint32_t b1) {
    asm volatile(
        "mma.sync.aligned.m16n8k16.row.col.f32.f16.f16.f32 "
        "{%0,%1,%2,%3}, {%4,%5,%6,%7}, {%8,%9}, {%0,%1,%2,%3};"
        : "+f"(c[0]), "+f"(c[1]), "+f"(c[2]), "+f"(c[3])
        : "r"(a[0]), "r"(a[1]), "r"(a[2]), "r"(a[3]), "r"(b0), "r"(b1));
}
__device__ __forceinline__ float tanh_fast(float x) {
    float y;
    asm("tanh.approx.f32 %0, %1;" : "=f"(y) : "f"(x));
    return y;
}

// ---------------- global scratch ----------------
__device__ float  ap_cb16[16][MDIM];              // cbias partials (16-way k split)
__device__ __half ap_Wt16[MDIM * MDIM];           // [n][k] = fp16(W1^T)
__device__ float  ap_partials[N_TILES * MDIM];    // per-CTA  sum_t e_t * x[t][col]
__device__ float  ap_sume[N_TILES];               // per-CTA  sum_t e_t

// ---------------- kernel 1: prep ----------------
// blocks 0-31: W1^T -> fp16.  blocks 32-47: cbias partials (16 k's each).
__global__ void __launch_bounds__(1024) ap_prep_kernel(const float* __restrict__ W1,
                                                       const float* __restrict__ W2,
                                                       const float* __restrict__ vm) {
    const int tid = threadIdx.x;
    if (blockIdx.x < 32) {
        const int n  = tid & 255;
        const int k0 = blockIdx.x * 8 + (tid >> 8) * 2;
        __half h0 = __float2half_rn(W1[k0 * MDIM + n]);         // coalesced in n
        __half h1 = __float2half_rn(W1[(k0 + 1) * MDIM + n]);
        __half2 hh = __halves2half2(h0, h1);
        *reinterpret_cast<__half2*>(ap_Wt16 + n * MDIM + k0) = hh;
    } else {
        __shared__ float part[4][MDIM];
        const int j  = blockIdx.x - 32;
        const int kq = tid >> 8;           // 0..3
        const int n  = tid & 255;
        float acc = 0.f;
        #pragma unroll
        for (int k0 = 0; k0 < 4; k0++) {
            int k = j * 16 + kq * 4 + k0;
            acc += vm[k] * W2[k * MDIM + n];
        }
        part[kq][n] = acc;
        __syncthreads();
        if (tid < MDIM)
            ap_cb16[j][tid] = part[0][tid] + part[1][tid] + part[2][tid] + part[3][tid];
    }
}

// ---------------- kernel 2: fused scores + exp + weighted partial sum ----------------
__global__ void __launch_bounds__(256, 2)
ap_scores_kernel(const float* __restrict__ x, const float* __restrict__ vm) {
    extern __shared__ char dsm[];
    __shared__ float2 cbvm[MDIM];            // 2 KB
    __shared__ float  sred[4][TILE_M];       // 1 KB

    const int tid   = threadIdx.x;
    const int wid   = tid >> 5;
    const int lane  = tid & 31;
    const int g     = lane >> 2;        // groupID
    const int tig   = lane & 3;         // thread-in-group
    const int mhalf = wid >> 2;         // rows 0-31 / 32-63
    const int nquad = wid & 3;          // cols q*64..
    const int m0    = mhalf * 32;
    const int n0    = nquad * 64;

    uint32_t raw  = smem_u32(dsm);
    uint32_t base = (raw + 1023u) & ~1023u;
    const uint32_t aA = base;                   // 64 x 264 halves
    const uint32_t aB = base + A_BYTES;         // 2 x (256 x 72 halves)
    // epilogue scratch aliased into the (then-dead) B region:
    char* dsm_base = dsm + (base - raw);
    float*  se   = reinterpret_cast<float*>(dsm_base + A_BYTES);          // 64 floats
    float4* spw4 = reinterpret_cast<float4*>(dsm_base + A_BYTES + 512);   // [4][64] float4

    const __half* wt = ap_Wt16;
    auto prefetchB = [&](int c) {
        uint32_t dstb = aB + (c & 1) * B_BYTES;
        #pragma unroll
        for (int it = 0; it < 8; it++) {
            int idx = it * 256 + tid;              // 0..2047
            int n = idx >> 3, jj = idx & 7;
            CP_ASYNC16(dstb + n * B_ROW_BYTES + jj * 16,
                       (const void*)(wt + n * MDIM + c * 64 + jj * 8));
        }
    };
    prefetchB(0);
    CP_COMMIT();

    // cbias reduction (16 L2-hot loads, overlapped with cp.async + x LDGs below)
    {
        float cb = 0.f;
        #pragma unroll
        for (int j = 0; j < 16; j++) cb += ap_cb16[j][tid];
        cbvm[tid] = make_float2(cb, vm[tid]);
    }

    // ---- load x tile (64 x 256 fp32) -> fp16 in smem ----
    const float* xt = x + (size_t)blockIdx.x * TILE_M * MDIM;
    #pragma unroll
    for (int it = 0; it < 8; it++) {
        int id   = it * 256 + tid;      // 0..2047 groups of 8 floats
        int row  = id >> 5;
        int col0 = (id & 31) * 8;
        float4 v0 = *(const float4*)(xt + row * MDIM + col0);
        float4 v1 = *(const float4*)(xt + row * MDIM + col0 + 4);
        __half2 h0 = __floats2half2_rn(v0.x, v0.y);
        __half2 h1 = __floats2half2_rn(v0.z, v0.w);
        __half2 h2 = __floats2half2_rn(v1.x, v1.y);
        __half2 h3 = __floats2half2_rn(v1.z, v1.w);
        sts_u128(aA + row * A_ROW_BYTES + col0 * 2,
                 *(uint32_t*)&h0, *(uint32_t*)&h1, *(uint32_t*)&h2, *(uint32_t*)&h3);
    }

    // ldmatrix address precompute (same mapping as R16, verified by bit-identical rel_err)
    const int l8 = lane & 7;
    const int lg = lane >> 3;           // 0..3
    uint32_t amat[2], bmat[4];
    #pragma unroll
    for (int mi = 0; mi < 2; mi++)
        amat[mi] = (uint32_t)(m0 + mi * 16 + (lg & 1) * 8 + l8) * A_ROW_BYTES
                 + (uint32_t)((lg >> 1) * 16);
    #pragma unroll
    for (int p = 0; p < 4; p++)
        bmat[p] = (uint32_t)(n0 + p * 16 + (lg >> 1) * 8 + l8) * B_ROW_BYTES
                + (uint32_t)((lg & 1) * 16);

    float acc[2][8][4];
    #pragma unroll
    for (int mi = 0; mi < 2; mi++)
        #pragma unroll
        for (int ni = 0; ni < 8; ni++)
            #pragma unroll
            for (int j = 0; j < 4; j++) acc[mi][ni][j] = 0.f;

    // ---- main loop: 4 K=64 chunks, double-buffered B, ldmatrix fragment loads ----
    #pragma unroll
    for (int c = 0; c < 4; c++) {
        if (c < 3) { prefetchB(c + 1); CP_COMMIT(); CP_WAIT1(); }
        else       { CP_WAIT0(); }
        __syncthreads();
        uint32_t abase = aA + c * 128;
        uint32_t bbase = aB + (c & 1) * B_BYTES;
        #pragma unroll
        for (int kk = 0; kk < 4; kk++) {
            uint32_t a[2][4];
            #pragma unroll
            for (int mi = 0; mi < 2; mi++)
                ldmatrix_x4(a[mi][0], a[mi][1], a[mi][2], a[mi][3],
                            abase + amat[mi] + kk * 32);
            #pragma unroll
            for (int p = 0; p < 4; p++) {
                uint32_t b0a, b1a, b0b, b1b;
                ldmatrix_x4(b0a, b1a, b0b, b1b, bbase + bmat[p] + kk * 32);
                #pragma unroll
                for (int mi = 0; mi < 2; mi++) {
                    mma16816(acc[mi][2 * p],     a[mi], b0a, b1a);
                    mma16816(acc[mi][2 * p + 1], a[mi], b0b, b1b);
                }
            }
        }
        __syncthreads();
    }

    // ---- epilogue A: score[r] = sum_col tanh(D + cb[col]) * vm[col] ----
    float rs[2][2];
    #pragma unroll
    for (int mi = 0; mi < 2; mi++) { rs[mi][0] = 0.f; rs[mi][1] = 0.f; }
    #pragma unroll
    for (int mi = 0; mi < 2; mi++)
        #pragma unroll
        for (int ni = 0; ni < 8; ni++)
            #pragma unroll
            for (int j = 0; j < 4; j++) {
                int col = n0 + ni * 8 + tig * 2 + (j & 1);
                float2 cv = cbvm[col];
                rs[mi][j >> 1] += tanh_fast(acc[mi][ni][j] + cv.x) * cv.y;
            }
    #pragma unroll
    for (int mi = 0; mi < 2; mi++)
        #pragma unroll
        for (int h = 0; h < 2; h++) {
            float v = rs[mi][h];
            v += __shfl_xor_sync(0xFFFFFFFFu, v, 1);
            v += __shfl_xor_sync(0xFFFFFFFFu, v, 2);
            if (tig == 0) sred[nquad][m0 + mi * 16 + h * 8 + g] = v;
        }
    __syncthreads();

    // ---- epilogue B: e = exp(score) (scores bounded; no max needed) ----
    if (tid < TILE_M) {
        float s = sred[0][tid] + sred[1][tid] + sred[2][tid] + sred[3][tid];
        se[tid] = __expf(s);
    }
    __syncthreads();

    // ---- epilogue C: partial[col] = sum_r e[r] * x_fp16[r][col]  (LDS.64, 4 cols/thread) ----
    {
        const int col4 = (tid & 63) * 4;    // 4 consecutive columns
        const int rg   = tid >> 6;          // row group 0..3 (16 rows each)
        float4 a4 = make_float4(0.f, 0.f, 0.f, 0.f);
        uint32_t ab = aA + (uint32_t)(rg * 16) * A_ROW_BYTES + (uint32_t)(col4 * 2);
        #pragma unroll 8
        for (int r = 0; r < 16; r++) {
            float e = se[rg * 16 + r];
            uint32_t p0, p1;
            lds_u64(p0, p1, ab + (uint32_t)r * A_ROW_BYTES);
            float2 x01 = __half22float2(*reinterpret_cast<__half2*>(&p0));
            float2 x23 = __half22float2(*reinterpret_cast<__half2*>(&p1));
            a4.x += e * x01.x; a4.y += e * x01.y;
            a4.z += e * x23.x; a4.w += e * x23.y;
        }
        spw4[rg * 64 + (tid & 63)] = a4;
    }
    // warp 4 computes sumE in parallel with the spw writes above
    if (wid == 4) {
        float s = se[lane] + se[lane + 32];
        #pragma unroll
        for (int o = 16; o > 0; o >>= 1) s += __shfl_xor_sync(0xFFFFFFFFu, s, o);
        if (lane == 0) ap_sume[blockIdx.x] = s;
    }
    __syncthreads();
    if (tid < 64) {
        float4 s0 = spw4[tid], s1 = spw4[64 + tid], s2 = spw4[128 + tid], s3 = spw4[192 + tid];
        float4 r = make_float4(s0.x + s1.x + s2.x + s3.x, s0.y + s1.y + s2.y + s3.y,
                               s0.z + s1.z + s2.z + s3.z, s0.w + s1.w + s2.w + s3.w);
        *(float4*)(ap_partials + (size_t)blockIdx.x * MDIM + tid * 4) = r;
    }
}

// ---------------- kernel 3: final reduce -> out (16,1,256) ----------------
__global__ void __launch_bounds__(256) ap_final2_kernel(float* __restrict__ out) {
    __shared__ float sp[8][32];
    __shared__ float swsum[8];
    const int b   = blockIdx.x;
    const int cg  = blockIdx.y;
    const int tid = threadIdx.x;
    const int col = cg * 32 + (tid & 31);
    const int rg  = tid >> 5;            // 0..7

    const float* pp = ap_partials + (size_t)b * TILES_PER_B * MDIM + col;
    float acc = 0.f;
    #pragma unroll
    for (int i = 0; i < 16; i++)
        acc += pp[(size_t)(rg * 16 + i) * MDIM];
    sp[rg][tid & 31] = acc;

    // sumE over 128 tiles: 8 warps x 16 values each
    {
        const int w = tid >> 5, l = tid & 31;
        float s = (l < 16) ? ap_sume[b * TILES_PER_B + w * 16 + l] : 0.f;
        #pragma unroll
        for (int o = 8; o > 0; o >>= 1) s += __shfl_xor_sync(0xFFFFFFFFu, s, o);
        if (l == 0) swsum[w] = s;
    }
    __syncthreads();
    if (tid < 32) {
        float r = 0.f, ssum = 0.f;
        #pragma unroll
        for (int q = 0; q < 8; q++) { r += sp[q][tid]; ssum += swsum[q]; }
        out[b * MDIM + col] = r / ssum;
    }
}

// ---------------- launch ----------------
extern "C" void kernel_launch(void* const* d_in, const int* in_sizes, int n_in,
                              void* d_out, int out_size) {
    const float* x  = (const float*)d_in[0];
    const float* W1 = (const float*)d_in[1];
    const float* W2 = (const float*)d_in[2];
    const float* vm = (const float*)d_in[3];
    float* out = (float*)d_out;

    cudaFuncSetAttribute(ap_scores_kernel, cudaFuncAttributeMaxDynamicSharedMemorySize, DYN_SMEM);

    ap_prep_kernel<<<48, 1024>>>(W1, W2, vm);
    ap_scores_kernel<<<N_TILES, 256, DYN_SMEM>>>(x, vm);
    ap_final2_kernel<<<dim3(BATCH, 8), 256>>>(out);
}